// round 11
// baseline (speedup 1.0000x reference)
#include <cuda_runtime.h>
#include <cuda_bf16.h>
#include <cstdint>

// Problem constants
#define BB 2
#define TT 2048
#define CC 1024
#define HH 16
#define DD 64
#define N1 (3*CC)   // 3072
#define M1 (BB*TT)  // 4096

// ---------------------------------------------------------------------------
// Scratch (device globals; no allocation allowed)
// ---------------------------------------------------------------------------
__device__ __nv_bfloat16 gQhi[BB*HH*TT*DD];  // [B][H][T][D], pre-scaled by 1/8
__device__ __nv_bfloat16 gQlo[BB*HH*TT*DD];
__device__ __nv_bfloat16 gKhi[BB*HH*TT*DD];
__device__ __nv_bfloat16 gKlo[BB*HH*TT*DD];
__device__ __nv_bfloat16 gVhi[BB*HH*TT*DD];
__device__ __nv_bfloat16 gVlo[BB*HH*TT*DD];

__device__ __nv_bfloat16 gXhi[M1*CC];      // x split
__device__ __nv_bfloat16 gXlo[M1*CC];
__device__ __nv_bfloat16 gWqkvThi[N1*CC];  // w_qkv transposed [N1][CC]
__device__ __nv_bfloat16 gWqkvTlo[N1*CC];
__device__ __nv_bfloat16 gWoThi[CC*CC];    // w_out transposed [CC][CC]
__device__ __nv_bfloat16 gWoTlo[CC*CC];
__device__ __nv_bfloat16 gOhi[M1*CC];      // attention output split
__device__ __nv_bfloat16 gOlo[M1*CC];

// ---------------------------------------------------------------------------
// PTX helpers (base compute_103-legal: ldmatrix / mma.sync / cp.async)
// ---------------------------------------------------------------------------
__device__ __forceinline__ uint32_t smem_u32(const void* p) {
    uint32_t a;
    asm("{ .reg .u64 t; cvta.to.shared.u64 t, %1; cvt.u32.u64 %0, t; }" : "=r"(a) : "l"(p));
    return a;
}
__device__ __forceinline__ void ldsm_x4(uint32_t addr, uint32_t& r0, uint32_t& r1,
                                        uint32_t& r2, uint32_t& r3) {
    asm volatile("ldmatrix.sync.aligned.m8n8.x4.shared.b16 {%0,%1,%2,%3}, [%4];"
                 : "=r"(r0), "=r"(r1), "=r"(r2), "=r"(r3) : "r"(addr));
}
__device__ __forceinline__ void ldsm_x4_t(uint32_t addr, uint32_t& r0, uint32_t& r1,
                                          uint32_t& r2, uint32_t& r3) {
    asm volatile("ldmatrix.sync.aligned.m8n8.x4.trans.shared.b16 {%0,%1,%2,%3}, [%4];"
                 : "=r"(r0), "=r"(r1), "=r"(r2), "=r"(r3) : "r"(addr));
}
__device__ __forceinline__ void mma16816(float* d, uint32_t a0, uint32_t a1,
                                         uint32_t a2, uint32_t a3,
                                         uint32_t b0, uint32_t b1) {
    asm volatile("mma.sync.aligned.m16n8k16.row.col.f32.bf16.bf16.f32 "
                 "{%0,%1,%2,%3}, {%4,%5,%6,%7}, {%8,%9}, {%0,%1,%2,%3};"
                 : "+f"(d[0]), "+f"(d[1]), "+f"(d[2]), "+f"(d[3])
                 : "r"(a0), "r"(a1), "r"(a2), "r"(a3), "r"(b0), "r"(b1));
}
__device__ __forceinline__ void cp16(uint32_t dst, const void* src) {
    asm volatile("cp.async.cg.shared.global [%0], [%1], 16;" :: "r"(dst), "l"(src));
}
__device__ __forceinline__ void cp_commit() {
    asm volatile("cp.async.commit_group;" ::: "memory");
}
template<int N>
__device__ __forceinline__ void cp_wait() {
    asm volatile("cp.async.wait_group %0;" :: "n"(N) : "memory");
}
__device__ __forceinline__ uint32_t packbf2(float x, float y) {
    __nv_bfloat162 t(__float2bfloat16_rn(x), __float2bfloat16_rn(y));
    return *(uint32_t*)&t;
}
__device__ __forceinline__ void store_split2(__nv_bfloat16* dh, __nv_bfloat16* dl,
                                             size_t idx, float v0, float v1) {
    __nv_bfloat16 h0 = __float2bfloat16_rn(v0), h1 = __float2bfloat16_rn(v1);
    *(__nv_bfloat162*)&dh[idx] = __nv_bfloat162(h0, h1);
    *(__nv_bfloat162*)&dl[idx] = __nv_bfloat162(
        __float2bfloat16_rn(v0 - __bfloat162float(h0)),
        __float2bfloat16_rn(v1 - __bfloat162float(h1)));
}
// packed 64B-row swizzle (GEMM tiles; k-chunk = 32 bf16 = 64B rows)
__device__ __forceinline__ uint32_t sw64(int row, int c) {
    return (uint32_t)(row * 64 + ((c ^ ((row >> 1) & 3)) * 16));
}
// packed 128B-row swizzle (attention tiles; D = 64 bf16 = 128B rows)
__device__ __forceinline__ uint32_t sw128p(int row, int c) {
    return (uint32_t)(row * 128 + ((c ^ (row & 7)) << 4));
}

// ---------------------------------------------------------------------------
// Fused conversion kernel (unchanged from R10)
// ---------------------------------------------------------------------------
#define CONV_XBLK   1024
#define CONV_WQBLK  ((N1/32)*(CC/32))   // 3072
#define CONV_WOBLK  ((CC/32)*(CC/32))   // 1024
#define CONV_GRID   (CONV_XBLK + CONV_WQBLK + CONV_WOBLK)  // 5120

__device__ __forceinline__ void transpose_split_block(
    const float* __restrict__ W, __nv_bfloat16* __restrict__ Thi,
    __nv_bfloat16* __restrict__ Tlo, int Nn, int nb, int kb, int tid,
    float (*t)[33])
{
    const int tx = tid & 31, ty = tid >> 5;     // 32 x 8
    const int n0 = nb * 32, k0 = kb * 32;
    #pragma unroll
    for (int r = 0; r < 4; r++)
        t[ty + 8 * r][tx] = W[(k0 + ty + 8 * r) * Nn + n0 + tx];
    __syncthreads();
    #pragma unroll
    for (int r = 0; r < 4; r++) {
        float v = t[tx][ty + 8 * r];
        __nv_bfloat16 h = __float2bfloat16_rn(v);
        float rem = v - __bfloat162float(h);
        int idx = (n0 + ty + 8 * r) * CC + k0 + tx;
        Thi[idx] = h;
        Tlo[idx] = __float2bfloat16_rn(rem);
    }
}

__global__ void __launch_bounds__(256) conv_all_kernel(
    const float4* __restrict__ x4,
    const float* __restrict__ w_qkv,
    const float* __restrict__ w_out,
    __nv_bfloat16* __restrict__ pXhi, __nv_bfloat16* __restrict__ pXlo,
    __nv_bfloat16* __restrict__ pWqh, __nv_bfloat16* __restrict__ pWql,
    __nv_bfloat16* __restrict__ pWoh, __nv_bfloat16* __restrict__ pWol)
{
    __shared__ float t[32][33];
    const int bid = blockIdx.x, tid = threadIdx.x;
    if (bid < CONV_XBLK) {
        const int n4 = M1 * CC / 4;
        for (int i = bid * 256 + tid; i < n4; i += CONV_XBLK * 256) {
            float4 v = x4[i];
            __nv_bfloat16 h0 = __float2bfloat16_rn(v.x), h1 = __float2bfloat16_rn(v.y);
            __nv_bfloat16 h2 = __float2bfloat16_rn(v.z), h3 = __float2bfloat16_rn(v.w);
            *(__nv_bfloat162*)&pXhi[4*i]   = __nv_bfloat162(h0, h1);
            *(__nv_bfloat162*)&pXhi[4*i+2] = __nv_bfloat162(h2, h3);
            *(__nv_bfloat162*)&pXlo[4*i]   = __nv_bfloat162(
                __float2bfloat16_rn(v.x - __bfloat162float(h0)),
                __float2bfloat16_rn(v.y - __bfloat162float(h1)));
            *(__nv_bfloat162*)&pXlo[4*i+2] = __nv_bfloat162(
                __float2bfloat16_rn(v.z - __bfloat162float(h2)),
                __float2bfloat16_rn(v.w - __bfloat162float(h3)));
        }
    } else if (bid < CONV_XBLK + CONV_WQBLK) {
        const int idx = bid - CONV_XBLK;
        transpose_split_block(w_qkv, pWqh, pWql, N1,
                              idx % (N1 / 32), idx / (N1 / 32), tid, t);
    } else {
        const int idx = bid - CONV_XBLK - CONV_WQBLK;
        transpose_split_block(w_out, pWoh, pWol, CC,
                              idx % (CC / 32), idx / (CC / 32), tid, t);
    }
}

// ---------------------------------------------------------------------------
// HMMA bf16-split GEMM — 512 threads, 16 warps (4m x 4n), warp tile 32x32.
// Same math/order per output element as the 8-warp version (bit-identical).
// 3-stage cp.async pipeline, one sync per chunk, final-iteration wait fix.
// ---------------------------------------------------------------------------
#define TILE_B  (128 * 64)              // 8192 bytes per operand tile
#define BUF_B   (4 * TILE_B)            // 32768 bytes per k-chunk stage
#define GEMM_SMEM (3 * BUF_B)           // 98304 bytes

template<int EPI>
__global__ void __launch_bounds__(512, 2) gemm_hmma_kernel(
    const __nv_bfloat16* __restrict__ Ahi, const __nv_bfloat16* __restrict__ Alo,
    const __nv_bfloat16* __restrict__ Bhi, const __nv_bfloat16* __restrict__ Blo,
    const float* __restrict__ bias, float* __restrict__ out)
{
    extern __shared__ char smem[];
    const uint32_t sb = smem_u32(smem);
    const int tid = threadIdx.x, wid = tid >> 5, lane = tid & 31;
    const int warp_m = wid & 3, warp_n = wid >> 2;       // 4 x 4 warps
    const int n0 = blockIdx.x * 128, m0 = blockIdx.y * 128;

    const __nv_bfloat16* srcs[4] = { Ahi, Alo, Bhi, Blo };
    const int row_u = tid >> 2;          // 0..127
    const int cu    = tid & 3;           // 16B unit within 64B row

    auto issue = [&](int chunk) {
        const int k0 = chunk * 32;
        const uint32_t dbase = sb + (chunk % 3) * BUF_B;
        #pragma unroll
        for (int ti = 0; ti < 4; ti++) {
            const int base = (ti < 2) ? m0 : n0;
            cp16(dbase + ti * TILE_B + sw64(row_u, cu),
                 &srcs[ti][(size_t)(base + row_u) * CC + k0 + cu * 8]);
        }
        cp_commit();
    };

    float acc[2][4][4];
    #pragma unroll
    for (int a = 0; a < 2; a++)
        #pragma unroll
        for (int b = 0; b < 4; b++)
            #pragma unroll
            for (int c = 0; c < 4; c++) acc[a][b][c] = 0.f;

    issue(0);
    issue(1);

    const int lrow = ((lane >> 3) & 1) * 8 + (lane & 7);
    const int lcu  = lane >> 4;

    const int NCH = CC / 32;
    for (int i = 0; i < NCH; i++) {
        if (i + 1 < NCH) cp_wait<1>(); else cp_wait<0>();
        __syncthreads();
        const uint32_t buf = sb + (i % 3) * BUF_B;

        #pragma unroll
        for (int ks = 0; ks < 2; ks++) {
            const int c16 = ks * 2 + lcu;
            uint32_t bh[2][4], bl[2][4];
            #pragma unroll
            for (int ng = 0; ng < 2; ng++) {
                const int rown = warp_n * 32 + ng * 16 + lrow;
                const uint32_t baddr = buf + 2 * TILE_B + sw64(rown, c16);
                ldsm_x4(baddr,          bh[ng][0], bh[ng][1], bh[ng][2], bh[ng][3]);
                ldsm_x4(baddr + TILE_B, bl[ng][0], bl[ng][1], bl[ng][2], bl[ng][3]);
            }
            #pragma unroll
            for (int mt = 0; mt < 2; mt++) {
                const int rowm = warp_m * 32 + mt * 16 + lrow;
                const uint32_t aaddr = buf + sw64(rowm, c16);
                uint32_t ah0, ah1, ah2, ah3, al0, al1, al2, al3;
                ldsm_x4(aaddr,          ah0, ah1, ah2, ah3);
                ldsm_x4(aaddr + TILE_B, al0, al1, al2, al3);
                #pragma unroll
                for (int nt = 0; nt < 4; nt++) {
                    const uint32_t b0h = bh[nt >> 1][nt & 1];
                    const uint32_t b1h = bh[nt >> 1][(nt & 1) + 2];
                    const uint32_t b0l = bl[nt >> 1][nt & 1];
                    const uint32_t b1l = bl[nt >> 1][(nt & 1) + 2];
                    mma16816(acc[mt][nt], ah0, ah1, ah2, ah3, b0h, b1h);
                    mma16816(acc[mt][nt], al0, al1, al2, al3, b0h, b1h);
                    mma16816(acc[mt][nt], ah0, ah1, ah2, ah3, b0l, b1l);
                }
            }
        }
        if (i + 2 < NCH) issue(i + 2);
    }

    const int ml = lane >> 2;
    const int nl = (lane & 3) * 2;
    #pragma unroll
    for (int mt = 0; mt < 2; mt++) {
        #pragma unroll
        for (int nt = 0; nt < 4; nt++) {
            const int m = m0 + warp_m * 32 + mt * 16 + ml;
            const int n = n0 + warp_n * 32 + nt * 8 + nl;
            const float bz0 = bias[n], bz1 = bias[n + 1];
            const float* a = acc[mt][nt];
            if (EPI == 0) {
                *(float2*)&out[(size_t)m * CC + n]       = make_float2(a[0] + bz0, a[1] + bz1);
                *(float2*)&out[(size_t)(m + 8) * CC + n] = make_float2(a[2] + bz0, a[3] + bz1);
            } else {
                const int s = n >> 10, rem = n & 1023;
                const int h = rem >> 6, d0 = rem & 63;
                float v0 = a[0] + bz0, v1 = a[1] + bz1;
                float v2 = a[2] + bz0, v3 = a[3] + bz1;
                if (s == 0) { v0 *= 0.125f; v1 *= 0.125f; v2 *= 0.125f; v3 *= 0.125f; }
                __nv_bfloat16* dh = (s == 0) ? gQhi : (s == 1) ? gKhi : gVhi;
                __nv_bfloat16* dl = (s == 0) ? gQlo : (s == 1) ? gKlo : gVlo;
                const int b0i = m >> 11, t0 = m & 2047;
                const int m8 = m + 8, b1i = m8 >> 11, t1 = m8 & 2047;
                size_t i0 = ((size_t)(b0i * HH + h) * TT + t0) * DD + d0;
                size_t i1 = ((size_t)(b1i * HH + h) * TT + t1) * DD + d0;
                store_split2(dh, dl, i0, v0, v1);
                store_split2(dh, dl, i1, v2, v3);
            }
        }
    }
}

// ---------------------------------------------------------------------------
// HMMA flash attention (causal).  R8/R10 structure, unchanged this round.
// ---------------------------------------------------------------------------
#define KT2 8192                      // 64 rows * 128B per operand tile
#define STG2 (4 * KT2)                // 32768 per kv stage
#define ATTN_SMEM (3 * STG2)          // 98304

__global__ void __launch_bounds__(256, 2) attn_mma_kernel()
{
    extern __shared__ char smem[];
    const uint32_t sb = smem_u32(smem);
    const int tid = threadIdx.x, wid = tid >> 5, lane = tid & 31;
    const int bh = blockIdx.y;
    const int qbase = (gridDim.x - 1 - blockIdx.x) * 128;   // heavy tiles first
    const size_t hoff = (size_t)bh * TT * DD;

    auto issueKV = [&](int tile) {
        const int kv0 = tile * 64;
        const uint32_t dbase = sb + ((tile + 2) % 3) * STG2;
        int u = tid;
        #pragma unroll
        for (int it = 0; it < 2; it++, u += 256) {
            const int row = u >> 3, c = u & 7;
            const size_t src = hoff + (size_t)(kv0 + row) * DD + c * 8;
            const uint32_t d = dbase + sw128p(row, c);
            cp16(d,           &gKhi[src]);
            cp16(d + KT2,     &gKlo[src]);
            cp16(d + 2 * KT2, &gVhi[src]);
            cp16(d + 3 * KT2, &gVlo[src]);
        }
        cp_commit();
    };

    // ---- prologue: Q into region 0 (two 64-row sub-tiles; hi then lo) ----
    {
        int u = tid;
        #pragma unroll
        for (int it = 0; it < 4; it++, u += 256) {
            const int row = u >> 3, c = u & 7;
            const size_t src = hoff + (size_t)(qbase + row) * DD + c * 8;
            const uint32_t dq = sb + (row >> 6) * KT2 + sw128p(row & 63, c);
            cp16(dq,           &gQhi[src]);
            cp16(dq + 2 * KT2, &gQlo[src]);
        }
        cp_commit();
    }
    issueKV(0);   // region 2

    const int ntiles = (qbase >> 6) + 2;

    // ---- Q fragments into registers ----
    const int lrow = ((lane >> 3) & 1) * 8 + (lane & 7);
    const int lcu  = lane >> 4;
    uint32_t qh[4][4], ql[4][4];
    cp_wait<1>();          // Q group done (KV0 may be in flight)
    __syncthreads();
    {
        const int qrow = wid * 16 + lrow;               // 0..127
        const uint32_t qtb = sb + (qrow >> 6) * KT2;    // sub-tile base
        const int qr = qrow & 63;
        #pragma unroll
        for (int ks = 0; ks < 4; ks++) {
            const uint32_t a = qtb + sw128p(qr, ks * 2 + lcu);
            ldsm_x4(a,           qh[ks][0], qh[ks][1], qh[ks][2], qh[ks][3]);
            ldsm_x4(a + 2 * KT2, ql[ks][0], ql[ks][1], ql[ks][2], ql[ks][3]);
        }
    }
    __syncthreads();       // everyone done reading Q smem
    issueKV(1);            // region 0 (overwrites Q area — now safe)

    float mrow0 = -1e30f, mrow1 = -1e30f, lsum0 = 0.f, lsum1 = 0.f;
    float O[8][4];
    #pragma unroll
    for (int i = 0; i < 8; i++)
        #pragma unroll
        for (int j = 0; j < 4; j++) O[i][j] = 0.f;

    const int r0g = qbase + wid * 16 + (lane >> 2);

    for (int t = 0; t < ntiles; t++) {
        if (t + 1 < ntiles) cp_wait<1>(); else cp_wait<0>();
        __syncthreads();
        const int kv0 = t * 64;
        const uint32_t kb = sb + ((t + 2) % 3) * STG2;

        // ---- S = Q K^T (3-pass split) ----
        float S[8][4];
        #pragma unroll
        for (int i = 0; i < 8; i++)
            #pragma unroll
            for (int j = 0; j < 4; j++) S[i][j] = 0.f;

        #pragma unroll
        for (int ks = 0; ks < 4; ks++) {
            #pragma unroll
            for (int ng = 0; ng < 4; ng++) {
                const int rown = ng * 16 + lrow;
                const uint32_t addr = kb + sw128p(rown, ks * 2 + lcu);
                uint32_t h0, h1, h2, h3, L0, L1, L2, L3;
                ldsm_x4(addr,       h0, h1, h2, h3);
                ldsm_x4(addr + KT2, L0, L1, L2, L3);
                mma16816(S[2*ng],   qh[ks][0], qh[ks][1], qh[ks][2], qh[ks][3], h0, h2);
                mma16816(S[2*ng],   ql[ks][0], ql[ks][1], ql[ks][2], ql[ks][3], h0, h2);
                mma16816(S[2*ng],   qh[ks][0], qh[ks][1], qh[ks][2], qh[ks][3], L0, L2);
                mma16816(S[2*ng+1], qh[ks][0], qh[ks][1], qh[ks][2], qh[ks][3], h1, h3);
                mma16816(S[2*ng+1], ql[ks][0], ql[ks][1], ql[ks][2], ql[ks][3], h1, h3);
                mma16816(S[2*ng+1], qh[ks][0], qh[ks][1], qh[ks][2], qh[ks][3], L1, L3);
            }
        }

        // ---- causal mask (only the two diagonal-crossing tiles) ----
        if (t + 2 >= ntiles) {
            #pragma unroll
            for (int nt = 0; nt < 8; nt++) {
                const int c0 = kv0 + nt * 8 + (lane & 3) * 2;
                if (c0     > r0g)     S[nt][0] = -1e30f;
                if (c0 + 1 > r0g)     S[nt][1] = -1e30f;
                if (c0     > r0g + 8) S[nt][2] = -1e30f;
                if (c0 + 1 > r0g + 8) S[nt][3] = -1e30f;
            }
        }

        // ---- online softmax ----
        float tm0 = -1e30f, tm1 = -1e30f;
        #pragma unroll
        for (int nt = 0; nt < 8; nt++) {
            tm0 = fmaxf(tm0, fmaxf(S[nt][0], S[nt][1]));
            tm1 = fmaxf(tm1, fmaxf(S[nt][2], S[nt][3]));
        }
        tm0 = fmaxf(tm0, __shfl_xor_sync(0xFFFFFFFFu, tm0, 1));
        tm0 = fmaxf(tm0, __shfl_xor_sync(0xFFFFFFFFu, tm0, 2));
        tm1 = fmaxf(tm1, __shfl_xor_sync(0xFFFFFFFFu, tm1, 1));
        tm1 = fmaxf(tm1, __shfl_xor_sync(0xFFFFFFFFu, tm1, 2));
        const float mn0 = fmaxf(mrow0, tm0), mn1 = fmaxf(mrow1, tm1);
        const float c0 = __expf(mrow0 - mn0), c1 = __expf(mrow1 - mn1);
        lsum0 *= c0; lsum1 *= c1;
        #pragma unroll
        for (int i = 0; i < 8; i++) {
            O[i][0] *= c0; O[i][1] *= c0; O[i][2] *= c1; O[i][3] *= c1;
        }
        mrow0 = mn0; mrow1 = mn1;

        // ---- P = exp(S - m); pack & P·V, interleaved per k16 ----
        #pragma unroll
        for (int f = 0; f < 4; f++) {
            const float p00 = __expf(S[2*f][0]   - mn0), p01 = __expf(S[2*f][1]   - mn0);
            const float p10 = __expf(S[2*f][2]   - mn1), p11 = __expf(S[2*f][3]   - mn1);
            const float p20 = __expf(S[2*f+1][0] - mn0), p21 = __expf(S[2*f+1][1] - mn0);
            const float p30 = __expf(S[2*f+1][2] - mn1), p31 = __expf(S[2*f+1][3] - mn1);
            lsum0 += p00 + p01 + p20 + p21;
            lsum1 += p10 + p11 + p30 + p31;
            const uint32_t pa0 = packbf2(p00, p01), pa1 = packbf2(p10, p11);
            const uint32_t pa2 = packbf2(p20, p21), pa3 = packbf2(p30, p31);
            const __nv_bfloat162* hp;
            hp = (const __nv_bfloat162*)&pa0;
            const uint32_t la0 = packbf2(p00 - __bfloat162float(hp->x), p01 - __bfloat162float(hp->y));
            hp = (const __nv_bfloat162*)&pa1;
            const uint32_t la1 = packbf2(p10 - __bfloat162float(hp->x), p11 - __bfloat162float(hp->y));
            hp = (const __nv_bfloat162*)&pa2;
            const uint32_t la2 = packbf2(p20 - __bfloat162float(hp->x), p21 - __bfloat162float(hp->y));
            hp = (const __nv_bfloat162*)&pa3;
            const uint32_t la3 = packbf2(p30 - __bfloat162float(hp->x), p31 - __bfloat162float(hp->y));

            const int kvr = f * 16 + ((lane >> 3) & 1) * 8 + (lane & 7);
            #pragma unroll
            for (int dg = 0; dg < 4; dg++) {
                const uint32_t addrV = kb + 2 * KT2 + sw128p(kvr, dg * 2 + lcu);
                uint32_t vh0, vh1, vh2, vh3, vl0, vl1, vl2, vl3;
                ldsm_x4_t(addrV,       vh0, vh1, vh2, vh3);
                ldsm_x4_t(addrV + KT2, vl0, vl1, vl2, vl3);
                mma16816(O[2*dg],   pa0, pa1, pa2, pa3, vh0, vh1);
                mma16816(O[2*dg],   la0, la1, la2, la3, vh0, vh1);
                mma16816(O[2*dg],   pa0, pa1, pa2, pa3, vl0, vl1);
                mma16816(O[2*dg+1], pa0, pa1, pa2, pa3, vh2, vh3);
                mma16816(O[2*dg+1], la0, la1, la2, la3, vh2, vh3);
                mma16816(O[2*dg+1], pa0, pa1, pa2, pa3, vl2, vl3);
            }
        }

        if (t + 2 < ntiles) issueKV(t + 2);
    }

    // ---- epilogue: normalize and store bf16 split ----
    float l0 = lsum0;
    l0 += __shfl_xor_sync(0xFFFFFFFFu, l0, 1);
    l0 += __shfl_xor_sync(0xFFFFFFFFu, l0, 2);
    float l1 = lsum1;
    l1 += __shfl_xor_sync(0xFFFFFFFFu, l1, 1);
    l1 += __shfl_xor_sync(0xFFFFFFFFu, l1, 2);
    const float inv0 = 1.f / l0, inv1 = 1.f / l1;

    const int b = bh >> 4, h = bh & 15;
    const size_t base0 = ((size_t)(b * TT + r0g)) * CC + h * DD;
    const size_t base1 = base0 + (size_t)8 * CC;
    #pragma unroll
    for (int dt = 0; dt < 8; dt++) {
        const int c = dt * 8 + (lane & 3) * 2;
        store_split2(gOhi, gOlo, base0 + c, O[dt][0] * inv0, O[dt][1] * inv0);
        store_split2(gOhi, gOlo, base1 + c, O[dt][2] * inv1, O[dt][3] * inv1);
    }
}

// ---------------------------------------------------------------------------
extern "C" void kernel_launch(void* const* d_in, const int* in_sizes, int n_in,
                              void* d_out, int out_size)
{
    const float* x     = (const float*)d_in[0];
    const float* w_qkv = (const float*)d_in[1];
    const float* b_qkv = (const float*)d_in[2];
    const float* w_out = (const float*)d_in[3];
    const float* b_out = (const float*)d_in[4];
    float* out = (float*)d_out;

    __nv_bfloat16 *pXhi, *pXlo, *pWqh, *pWql, *pWoh, *pWol, *pOhi, *pOlo;
    cudaGetSymbolAddress((void**)&pXhi, gXhi);
    cudaGetSymbolAddress((void**)&pXlo, gXlo);
    cudaGetSymbolAddress((void**)&pWqh, gWqkvThi);
    cudaGetSymbolAddress((void**)&pWql, gWqkvTlo);
    cudaGetSymbolAddress((void**)&pWoh, gWoThi);
    cudaGetSymbolAddress((void**)&pWol, gWoTlo);
    cudaGetSymbolAddress((void**)&pOhi, gOhi);
    cudaGetSymbolAddress((void**)&pOlo, gOlo);

    cudaFuncSetAttribute(attn_mma_kernel,
                         cudaFuncAttributeMaxDynamicSharedMemorySize, ATTN_SMEM);
    cudaFuncSetAttribute(gemm_hmma_kernel<0>,
                         cudaFuncAttributeMaxDynamicSharedMemorySize, GEMM_SMEM);
    cudaFuncSetAttribute(gemm_hmma_kernel<1>,
                         cudaFuncAttributeMaxDynamicSharedMemorySize, GEMM_SMEM);

    // fused input conversions (x split + both weight transposes)
    conv_all_kernel<<<CONV_GRID, 256>>>((const float4*)x, w_qkv, w_out,
                                        pXhi, pXlo, pWqh, pWql, pWoh, pWol);

    // QKV projection -> Q/K/V bf16 hi/lo, [B,H,T,D] (Q pre-scaled 1/8)
    gemm_hmma_kernel<1><<<dim3(N1 / 128, M1 / 128), 512, GEMM_SMEM>>>(
        pXhi, pXlo, pWqh, pWql, b_qkv, nullptr);

    // flash attention -> gOhi/gOlo
    attn_mma_kernel<<<dim3(TT / 128, BB * HH), 256, ATTN_SMEM>>>();

    // output projection -> out
    gemm_hmma_kernel<0><<<dim3(CC / 128, M1 / 128), 512, GEMM_SMEM>>>(
        pOhi, pOlo, pWoh, pWol, b_out, out);
}

// round 13
// speedup vs baseline: 1.0449x; 1.0449x over previous
#include <cuda_runtime.h>
#include <cuda_bf16.h>
#include <cstdint>

// Problem constants
#define BB 2
#define TT 2048
#define CC 1024
#define HH 16
#define DD 64
#define N1 (3*CC)   // 3072
#define M1 (BB*TT)  // 4096

// ---------------------------------------------------------------------------
// Scratch (device globals; no allocation allowed)
// ---------------------------------------------------------------------------
__device__ __nv_bfloat16 gQhi[BB*HH*TT*DD];  // [B][H][T][D], pre-scaled by 1/8
__device__ __nv_bfloat16 gQlo[BB*HH*TT*DD];
__device__ __nv_bfloat16 gKhi[BB*HH*TT*DD];
__device__ __nv_bfloat16 gKlo[BB*HH*TT*DD];
__device__ __nv_bfloat16 gVhi[BB*HH*TT*DD];
__device__ __nv_bfloat16 gVlo[BB*HH*TT*DD];

__device__ __nv_bfloat16 gXhi[M1*CC];      // x split
__device__ __nv_bfloat16 gXlo[M1*CC];
__device__ __nv_bfloat16 gWqkvThi[N1*CC];  // w_qkv transposed [N1][CC]
__device__ __nv_bfloat16 gWqkvTlo[N1*CC];
__device__ __nv_bfloat16 gWoThi[CC*CC];    // w_out transposed [CC][CC]
__device__ __nv_bfloat16 gWoTlo[CC*CC];
__device__ __nv_bfloat16 gOhi[M1*CC];      // attention output split
__device__ __nv_bfloat16 gOlo[M1*CC];

// ---------------------------------------------------------------------------
// PTX helpers (base compute_103-legal: ldmatrix / mma.sync / cp.async)
// ---------------------------------------------------------------------------
__device__ __forceinline__ uint32_t smem_u32(const void* p) {
    uint32_t a;
    asm("{ .reg .u64 t; cvta.to.shared.u64 t, %1; cvt.u32.u64 %0, t; }" : "=r"(a) : "l"(p));
    return a;
}
__device__ __forceinline__ void ldsm_x4(uint32_t addr, uint32_t& r0, uint32_t& r1,
                                        uint32_t& r2, uint32_t& r3) {
    asm volatile("ldmatrix.sync.aligned.m8n8.x4.shared.b16 {%0,%1,%2,%3}, [%4];"
                 : "=r"(r0), "=r"(r1), "=r"(r2), "=r"(r3) : "r"(addr));
}
__device__ __forceinline__ void ldsm_x4_t(uint32_t addr, uint32_t& r0, uint32_t& r1,
                                          uint32_t& r2, uint32_t& r3) {
    asm volatile("ldmatrix.sync.aligned.m8n8.x4.trans.shared.b16 {%0,%1,%2,%3}, [%4];"
                 : "=r"(r0), "=r"(r1), "=r"(r2), "=r"(r3) : "r"(addr));
}
__device__ __forceinline__ void mma16816(float* d, uint32_t a0, uint32_t a1,
                                         uint32_t a2, uint32_t a3,
                                         uint32_t b0, uint32_t b1) {
    asm volatile("mma.sync.aligned.m16n8k16.row.col.f32.bf16.bf16.f32 "
                 "{%0,%1,%2,%3}, {%4,%5,%6,%7}, {%8,%9}, {%0,%1,%2,%3};"
                 : "+f"(d[0]), "+f"(d[1]), "+f"(d[2]), "+f"(d[3])
                 : "r"(a0), "r"(a1), "r"(a2), "r"(a3), "r"(b0), "r"(b1));
}
__device__ __forceinline__ void cp16(uint32_t dst, const void* src) {
    asm volatile("cp.async.cg.shared.global [%0], [%1], 16;" :: "r"(dst), "l"(src));
}
__device__ __forceinline__ void cp_commit() {
    asm volatile("cp.async.commit_group;" ::: "memory");
}
template<int N>
__device__ __forceinline__ void cp_wait() {
    asm volatile("cp.async.wait_group %0;" :: "n"(N) : "memory");
}
__device__ __forceinline__ uint32_t packbf2(float x, float y) {
    __nv_bfloat162 t(__float2bfloat16_rn(x), __float2bfloat16_rn(y));
    return *(uint32_t*)&t;
}
__device__ __forceinline__ void store_split2(__nv_bfloat16* dh, __nv_bfloat16* dl,
                                             size_t idx, float v0, float v1) {
    __nv_bfloat16 h0 = __float2bfloat16_rn(v0), h1 = __float2bfloat16_rn(v1);
    *(__nv_bfloat162*)&dh[idx] = __nv_bfloat162(h0, h1);
    *(__nv_bfloat162*)&dl[idx] = __nv_bfloat162(
        __float2bfloat16_rn(v0 - __bfloat162float(h0)),
        __float2bfloat16_rn(v1 - __bfloat162float(h1)));
}
// packed 64B-row swizzle (GEMM tiles; k-chunk = 32 bf16 = 64B rows)
__device__ __forceinline__ uint32_t sw64(int row, int c) {
    return (uint32_t)(row * 64 + ((c ^ ((row >> 1) & 3)) * 16));
}
// packed 128B-row swizzle (attention tiles; D = 64 bf16 = 128B rows)
__device__ __forceinline__ uint32_t sw128p(int row, int c) {
    return (uint32_t)(row * 128 + ((c ^ (row & 7)) << 4));
}

// ---------------------------------------------------------------------------
// Fused conversion kernel: x-split gets 2048 blocks (it carries ~half the
// traffic), then w_qkv / w_out transpose+split blocks.
// ---------------------------------------------------------------------------
#define CONV_XBLK   2048
#define CONV_WQBLK  ((N1/32)*(CC/32))   // 3072
#define CONV_WOBLK  ((CC/32)*(CC/32))   // 1024
#define CONV_GRID   (CONV_XBLK + CONV_WQBLK + CONV_WOBLK)  // 6144

__device__ __forceinline__ void transpose_split_block(
    const float* __restrict__ W, __nv_bfloat16* __restrict__ Thi,
    __nv_bfloat16* __restrict__ Tlo, int Nn, int nb, int kb, int tid,
    float (*t)[33])
{
    const int tx = tid & 31, ty = tid >> 5;     // 32 x 8
    const int n0 = nb * 32, k0 = kb * 32;
    #pragma unroll
    for (int r = 0; r < 4; r++)
        t[ty + 8 * r][tx] = W[(k0 + ty + 8 * r) * Nn + n0 + tx];
    __syncthreads();
    #pragma unroll
    for (int r = 0; r < 4; r++) {
        float v = t[tx][ty + 8 * r];
        __nv_bfloat16 h = __float2bfloat16_rn(v);
        float rem = v - __bfloat162float(h);
        int idx = (n0 + ty + 8 * r) * CC + k0 + tx;
        Thi[idx] = h;
        Tlo[idx] = __float2bfloat16_rn(rem);
    }
}

__global__ void __launch_bounds__(256) conv_all_kernel(
    const float4* __restrict__ x4,
    const float* __restrict__ w_qkv,
    const float* __restrict__ w_out,
    __nv_bfloat16* __restrict__ pXhi, __nv_bfloat16* __restrict__ pXlo,
    __nv_bfloat16* __restrict__ pWqh, __nv_bfloat16* __restrict__ pWql,
    __nv_bfloat16* __restrict__ pWoh, __nv_bfloat16* __restrict__ pWol)
{
    __shared__ float t[32][33];
    const int bid = blockIdx.x, tid = threadIdx.x;
    if (bid < CONV_XBLK) {
        const int n4 = M1 * CC / 4;
        for (int i = bid * 256 + tid; i < n4; i += CONV_XBLK * 256) {
            float4 v = x4[i];
            __nv_bfloat16 h0 = __float2bfloat16_rn(v.x), h1 = __float2bfloat16_rn(v.y);
            __nv_bfloat16 h2 = __float2bfloat16_rn(v.z), h3 = __float2bfloat16_rn(v.w);
            *(__nv_bfloat162*)&pXhi[4*i]   = __nv_bfloat162(h0, h1);
            *(__nv_bfloat162*)&pXhi[4*i+2] = __nv_bfloat162(h2, h3);
            *(__nv_bfloat162*)&pXlo[4*i]   = __nv_bfloat162(
                __float2bfloat16_rn(v.x - __bfloat162float(h0)),
                __float2bfloat16_rn(v.y - __bfloat162float(h1)));
            *(__nv_bfloat162*)&pXlo[4*i+2] = __nv_bfloat162(
                __float2bfloat16_rn(v.z - __bfloat162float(h2)),
                __float2bfloat16_rn(v.w - __bfloat162float(h3)));
        }
    } else if (bid < CONV_XBLK + CONV_WQBLK) {
        const int idx = bid - CONV_XBLK;
        transpose_split_block(w_qkv, pWqh, pWql, N1,
                              idx % (N1 / 32), idx / (N1 / 32), tid, t);
    } else {
        const int idx = bid - CONV_XBLK - CONV_WQBLK;
        transpose_split_block(w_out, pWoh, pWol, CC,
                              idx % (CC / 32), idx / (CC / 32), tid, t);
    }
}

// ---------------------------------------------------------------------------
// HMMA bf16-split GEMM (R10 structure: 256 threads, 8 warps 2m x 4n,
// warp tile 64x32, 3-stage cp.async, one sync/chunk, last-iter full wait).
// EPI=0: fp32 out + bias.  EPI=1: QKV scatter bf16 hi/lo (Q pre-scaled 1/8).
// ---------------------------------------------------------------------------
#define TILE_B  (128 * 64)              // 8192 bytes per operand tile
#define BUF_B   (4 * TILE_B)            // 32768 bytes per k-chunk stage
#define GEMM_SMEM (3 * BUF_B)           // 98304 bytes

template<int EPI>
__global__ void __launch_bounds__(256, 2) gemm_hmma_kernel(
    const __nv_bfloat16* __restrict__ Ahi, const __nv_bfloat16* __restrict__ Alo,
    const __nv_bfloat16* __restrict__ Bhi, const __nv_bfloat16* __restrict__ Blo,
    const float* __restrict__ bias, float* __restrict__ out)
{
    extern __shared__ char smem[];
    const uint32_t sb = smem_u32(smem);
    const int tid = threadIdx.x, wid = tid >> 5, lane = tid & 31;
    const int warp_m = wid & 1, warp_n = wid >> 1;
    const int n0 = blockIdx.x * 128, m0 = blockIdx.y * 128;

    const __nv_bfloat16* srcs[4] = { Ahi, Alo, Bhi, Blo };
    const int row_u = tid >> 2;
    const int cu    = tid & 3;

    auto issue = [&](int chunk) {
        const int k0 = chunk * 32;
        const uint32_t dbase = sb + (chunk % 3) * BUF_B;
        #pragma unroll
        for (int ti = 0; ti < 4; ti++) {
            const int base = (ti < 2) ? m0 : n0;
            const __nv_bfloat16* s = srcs[ti];
            #pragma unroll
            for (int j = 0; j < 2; j++) {
                const int row = row_u + j * 64;
                cp16(dbase + ti * TILE_B + sw64(row, cu),
                     &s[(size_t)(base + row) * CC + k0 + cu * 8]);
            }
        }
        cp_commit();
    };

    float acc[4][4][4];
    #pragma unroll
    for (int a = 0; a < 4; a++)
        #pragma unroll
        for (int b = 0; b < 4; b++)
            #pragma unroll
            for (int c = 0; c < 4; c++) acc[a][b][c] = 0.f;

    issue(0);
    issue(1);

    const int lrow = ((lane >> 3) & 1) * 8 + (lane & 7);
    const int lcu  = lane >> 4;

    const int NCH = CC / 32;
    for (int i = 0; i < NCH; i++) {
        if (i + 1 < NCH) cp_wait<1>(); else cp_wait<0>();
        __syncthreads();
        const uint32_t buf = sb + (i % 3) * BUF_B;

        #pragma unroll
        for (int ks = 0; ks < 2; ks++) {
            const int c16 = ks * 2 + lcu;
            uint32_t bh[2][4], bl[2][4];
            #pragma unroll
            for (int ng = 0; ng < 2; ng++) {
                const int rown = warp_n * 32 + ng * 16 + lrow;
                const uint32_t baddr = buf + 2 * TILE_B + sw64(rown, c16);
                ldsm_x4(baddr,          bh[ng][0], bh[ng][1], bh[ng][2], bh[ng][3]);
                ldsm_x4(baddr + TILE_B, bl[ng][0], bl[ng][1], bl[ng][2], bl[ng][3]);
            }
            #pragma unroll
            for (int mt = 0; mt < 4; mt++) {
                const int rowm = warp_m * 64 + mt * 16 + lrow;
                const uint32_t aaddr = buf + sw64(rowm, c16);
                uint32_t ah0, ah1, ah2, ah3, al0, al1, al2, al3;
                ldsm_x4(aaddr,          ah0, ah1, ah2, ah3);
                ldsm_x4(aaddr + TILE_B, al0, al1, al2, al3);
                #pragma unroll
                for (int nt = 0; nt < 4; nt++) {
                    const uint32_t b0h = bh[nt >> 1][nt & 1];
                    const uint32_t b1h = bh[nt >> 1][(nt & 1) + 2];
                    const uint32_t b0l = bl[nt >> 1][nt & 1];
                    const uint32_t b1l = bl[nt >> 1][(nt & 1) + 2];
                    mma16816(acc[mt][nt], ah0, ah1, ah2, ah3, b0h, b1h);
                    mma16816(acc[mt][nt], al0, al1, al2, al3, b0h, b1h);
                    mma16816(acc[mt][nt], ah0, ah1, ah2, ah3, b0l, b1l);
                }
            }
        }
        if (i + 2 < NCH) issue(i + 2);
    }

    const int ml = lane >> 2;
    const int nl = (lane & 3) * 2;
    #pragma unroll
    for (int mt = 0; mt < 4; mt++) {
        #pragma unroll
        for (int nt = 0; nt < 4; nt++) {
            const int m = m0 + warp_m * 64 + mt * 16 + ml;
            const int n = n0 + warp_n * 32 + nt * 8 + nl;
            const float bz0 = bias[n], bz1 = bias[n + 1];
            const float* a = acc[mt][nt];
            if (EPI == 0) {
                *(float2*)&out[(size_t)m * CC + n]       = make_float2(a[0] + bz0, a[1] + bz1);
                *(float2*)&out[(size_t)(m + 8) * CC + n] = make_float2(a[2] + bz0, a[3] + bz1);
            } else {
                const int s = n >> 10, rem = n & 1023;
                const int h = rem >> 6, d0 = rem & 63;
                float v0 = a[0] + bz0, v1 = a[1] + bz1;
                float v2 = a[2] + bz0, v3 = a[3] + bz1;
                if (s == 0) { v0 *= 0.125f; v1 *= 0.125f; v2 *= 0.125f; v3 *= 0.125f; }
                __nv_bfloat16* dh = (s == 0) ? gQhi : (s == 1) ? gKhi : gVhi;
                __nv_bfloat16* dl = (s == 0) ? gQlo : (s == 1) ? gKlo : gVlo;
                const int b0i = m >> 11, t0 = m & 2047;
                const int m8 = m + 8, b1i = m8 >> 11, t1 = m8 & 2047;
                size_t i0 = ((size_t)(b0i * HH + h) * TT + t0) * DD + d0;
                size_t i1 = ((size_t)(b1i * HH + h) * TT + t1) * DD + d0;
                store_split2(dh, dl, i0, v0, v1);
                store_split2(dh, dl, i1, v2, v3);
            }
        }
    }
}

// ---------------------------------------------------------------------------
// HMMA flash attention (causal).  R10 structure: packed SW128 tiles, 3-stage
// KV ring reusing the Q region, one sync per kv tile, heavy q-tiles first.
// ---------------------------------------------------------------------------
#define KT2 8192                      // 64 rows * 128B per operand tile
#define STG2 (4 * KT2)                // 32768 per kv stage
#define ATTN_SMEM (3 * STG2)          // 98304

__global__ void __launch_bounds__(256, 2) attn_mma_kernel()
{
    extern __shared__ char smem[];
    const uint32_t sb = smem_u32(smem);
    const int tid = threadIdx.x, wid = tid >> 5, lane = tid & 31;
    const int bh = blockIdx.y;
    const int qbase = (gridDim.x - 1 - blockIdx.x) * 128;   // heavy tiles first
    const size_t hoff = (size_t)bh * TT * DD;

    auto issueKV = [&](int tile) {
        const int kv0 = tile * 64;
        const uint32_t dbase = sb + ((tile + 2) % 3) * STG2;
        int u = tid;
        #pragma unroll
        for (int it = 0; it < 2; it++, u += 256) {
            const int row = u >> 3, c = u & 7;
            const size_t src = hoff + (size_t)(kv0 + row) * DD + c * 8;
            const uint32_t d = dbase + sw128p(row, c);
            cp16(d,           &gKhi[src]);
            cp16(d + KT2,     &gKlo[src]);
            cp16(d + 2 * KT2, &gVhi[src]);
            cp16(d + 3 * KT2, &gVlo[src]);
        }
        cp_commit();
    };

    // ---- prologue: Q into region 0 (two 64-row sub-tiles; hi then lo) ----
    {
        int u = tid;
        #pragma unroll
        for (int it = 0; it < 4; it++, u += 256) {
            const int row = u >> 3, c = u & 7;
            const size_t src = hoff + (size_t)(qbase + row) * DD + c * 8;
            const uint32_t dq = sb + (row >> 6) * KT2 + sw128p(row & 63, c);
            cp16(dq,           &gQhi[src]);
            cp16(dq + 2 * KT2, &gQlo[src]);
        }
        cp_commit();
    }
    issueKV(0);   // region 2

    const int ntiles = (qbase >> 6) + 2;

    // ---- Q fragments into registers ----
    const int lrow = ((lane >> 3) & 1) * 8 + (lane & 7);
    const int lcu  = lane >> 4;
    uint32_t qh[4][4], ql[4][4];
    cp_wait<1>();          // Q group done (KV0 may be in flight)
    __syncthreads();
    {
        const int qrow = wid * 16 + lrow;               // 0..127
        const uint32_t qtb = sb + (qrow >> 6) * KT2;    // sub-tile base
        const int qr = qrow & 63;
        #pragma unroll
        for (int ks = 0; ks < 4; ks++) {
            const uint32_t a = qtb + sw128p(qr, ks * 2 + lcu);
            ldsm_x4(a,           qh[ks][0], qh[ks][1], qh[ks][2], qh[ks][3]);
            ldsm_x4(a + 2 * KT2, ql[ks][0], ql[ks][1], ql[ks][2], ql[ks][3]);
        }
    }
    __syncthreads();       // everyone done reading Q smem
    issueKV(1);            // region 0 (overwrites Q area — now safe)

    float mrow0 = -1e30f, mrow1 = -1e30f, lsum0 = 0.f, lsum1 = 0.f;
    float O[8][4];
    #pragma unroll
    for (int i = 0; i < 8; i++)
        #pragma unroll
        for (int j = 0; j < 4; j++) O[i][j] = 0.f;

    const int r0g = qbase + wid * 16 + (lane >> 2);

    for (int t = 0; t < ntiles; t++) {
        if (t + 1 < ntiles) cp_wait<1>(); else cp_wait<0>();
        __syncthreads();
        const int kv0 = t * 64;
        const uint32_t kb = sb + ((t + 2) % 3) * STG2;

        // ---- S = Q K^T (3-pass split) ----
        float S[8][4];
        #pragma unroll
        for (int i = 0; i < 8; i++)
            #pragma unroll
            for (int j = 0; j < 4; j++) S[i][j] = 0.f;

        #pragma unroll
        for (int ks = 0; ks < 4; ks++) {
            #pragma unroll
            for (int ng = 0; ng < 4; ng++) {
                const int rown = ng * 16 + lrow;
                const uint32_t addr = kb + sw128p(rown, ks * 2 + lcu);
                uint32_t h0, h1, h2, h3, L0, L1, L2, L3;
                ldsm_x4(addr,       h0, h1, h2, h3);
                ldsm_x4(addr + KT2, L0, L1, L2, L3);
                mma16816(S[2*ng],   qh[ks][0], qh[ks][1], qh[ks][2], qh[ks][3], h0, h2);
                mma16816(S[2*ng],   ql[ks][0], ql[ks][1], ql[ks][2], ql[ks][3], h0, h2);
                mma16816(S[2*ng],   qh[ks][0], qh[ks][1], qh[ks][2], qh[ks][3], L0, L2);
                mma16816(S[2*ng+1], qh[ks][0], qh[ks][1], qh[ks][2], qh[ks][3], h1, h3);
                mma16816(S[2*ng+1], ql[ks][0], ql[ks][1], ql[ks][2], ql[ks][3], h1, h3);
                mma16816(S[2*ng+1], qh[ks][0], qh[ks][1], qh[ks][2], qh[ks][3], L1, L3);
            }
        }

        // ---- causal mask (only the two diagonal-crossing tiles) ----
        if (t + 2 >= ntiles) {
            #pragma unroll
            for (int nt = 0; nt < 8; nt++) {
                const int c0 = kv0 + nt * 8 + (lane & 3) * 2;
                if (c0     > r0g)     S[nt][0] = -1e30f;
                if (c0 + 1 > r0g)     S[nt][1] = -1e30f;
                if (c0     > r0g + 8) S[nt][2] = -1e30f;
                if (c0 + 1 > r0g + 8) S[nt][3] = -1e30f;
            }
        }

        // ---- online softmax ----
        float tm0 = -1e30f, tm1 = -1e30f;
        #pragma unroll
        for (int nt = 0; nt < 8; nt++) {
            tm0 = fmaxf(tm0, fmaxf(S[nt][0], S[nt][1]));
            tm1 = fmaxf(tm1, fmaxf(S[nt][2], S[nt][3]));
        }
        tm0 = fmaxf(tm0, __shfl_xor_sync(0xFFFFFFFFu, tm0, 1));
        tm0 = fmaxf(tm0, __shfl_xor_sync(0xFFFFFFFFu, tm0, 2));
        tm1 = fmaxf(tm1, __shfl_xor_sync(0xFFFFFFFFu, tm1, 1));
        tm1 = fmaxf(tm1, __shfl_xor_sync(0xFFFFFFFFu, tm1, 2));
        const float mn0 = fmaxf(mrow0, tm0), mn1 = fmaxf(mrow1, tm1);
        const float c0 = __expf(mrow0 - mn0), c1 = __expf(mrow1 - mn1);
        lsum0 *= c0; lsum1 *= c1;
        #pragma unroll
        for (int i = 0; i < 8; i++) {
            O[i][0] *= c0; O[i][1] *= c0; O[i][2] *= c1; O[i][3] *= c1;
        }
        mrow0 = mn0; mrow1 = mn1;

        // ---- P = exp(S - m); pack & P·V, interleaved per k16 ----
        #pragma unroll
        for (int f = 0; f < 4; f++) {
            const float p00 = __expf(S[2*f][0]   - mn0), p01 = __expf(S[2*f][1]   - mn0);
            const float p10 = __expf(S[2*f][2]   - mn1), p11 = __expf(S[2*f][3]   - mn1);
            const float p20 = __expf(S[2*f+1][0] - mn0), p21 = __expf(S[2*f+1][1] - mn0);
            const float p30 = __expf(S[2*f+1][2] - mn1), p31 = __expf(S[2*f+1][3] - mn1);
            lsum0 += p00 + p01 + p20 + p21;
            lsum1 += p10 + p11 + p30 + p31;
            const uint32_t pa0 = packbf2(p00, p01), pa1 = packbf2(p10, p11);
            const uint32_t pa2 = packbf2(p20, p21), pa3 = packbf2(p30, p31);
            const __nv_bfloat162* hp;
            hp = (const __nv_bfloat162*)&pa0;
            const uint32_t la0 = packbf2(p00 - __bfloat162float(hp->x), p01 - __bfloat162float(hp->y));
            hp = (const __nv_bfloat162*)&pa1;
            const uint32_t la1 = packbf2(p10 - __bfloat162float(hp->x), p11 - __bfloat162float(hp->y));
            hp = (const __nv_bfloat162*)&pa2;
            const uint32_t la2 = packbf2(p20 - __bfloat162float(hp->x), p21 - __bfloat162float(hp->y));
            hp = (const __nv_bfloat162*)&pa3;
            const uint32_t la3 = packbf2(p30 - __bfloat162float(hp->x), p31 - __bfloat162float(hp->y));

            const int kvr = f * 16 + ((lane >> 3) & 1) * 8 + (lane & 7);
            #pragma unroll
            for (int dg = 0; dg < 4; dg++) {
                const uint32_t addrV = kb + 2 * KT2 + sw128p(kvr, dg * 2 + lcu);
                uint32_t vh0, vh1, vh2, vh3, vl0, vl1, vl2, vl3;
                ldsm_x4_t(addrV,       vh0, vh1, vh2, vh3);
                ldsm_x4_t(addrV + KT2, vl0, vl1, vl2, vl3);
                mma16816(O[2*dg],   pa0, pa1, pa2, pa3, vh0, vh1);
                mma16816(O[2*dg],   la0, la1, la2, la3, vh0, vh1);
                mma16816(O[2*dg],   pa0, pa1, pa2, pa3, vl0, vl1);
                mma16816(O[2*dg+1], pa0, pa1, pa2, pa3, vh2, vh3);
                mma16816(O[2*dg+1], la0, la1, la2, la3, vh2, vh3);
                mma16816(O[2*dg+1], pa0, pa1, pa2, pa3, vl2, vl3);
            }
        }

        if (t + 2 < ntiles) issueKV(t + 2);
    }

    // ---- epilogue: normalize and store bf16 split ----
    float l0 = lsum0;
    l0 += __shfl_xor_sync(0xFFFFFFFFu, l0, 1);
    l0 += __shfl_xor_sync(0xFFFFFFFFu, l0, 2);
    float l1 = lsum1;
    l1 += __shfl_xor_sync(0xFFFFFFFFu, l1, 1);
    l1 += __shfl_xor_sync(0xFFFFFFFFu, l1, 2);
    const float inv0 = 1.f / l0, inv1 = 1.f / l1;

    const int b = bh >> 4, h = bh & 15;
    const size_t base0 = ((size_t)(b * TT + r0g)) * CC + h * DD;
    const size_t base1 = base0 + (size_t)8 * CC;
    #pragma unroll
    for (int dt = 0; dt < 8; dt++) {
        const int c = dt * 8 + (lane & 3) * 2;
        store_split2(gOhi, gOlo, base0 + c, O[dt][0] * inv0, O[dt][1] * inv0);
        store_split2(gOhi, gOlo, base1 + c, O[dt][2] * inv1, O[dt][3] * inv1);
    }
}

// ---------------------------------------------------------------------------
extern "C" void kernel_launch(void* const* d_in, const int* in_sizes, int n_in,
                              void* d_out, int out_size)
{
    const float* x     = (const float*)d_in[0];
    const float* w_qkv = (const float*)d_in[1];
    const float* b_qkv = (const float*)d_in[2];
    const float* w_out = (const float*)d_in[3];
    const float* b_out = (const float*)d_in[4];
    float* out = (float*)d_out;

    __nv_bfloat16 *pXhi, *pXlo, *pWqh, *pWql, *pWoh, *pWol, *pOhi, *pOlo;
    cudaGetSymbolAddress((void**)&pXhi, gXhi);
    cudaGetSymbolAddress((void**)&pXlo, gXlo);
    cudaGetSymbolAddress((void**)&pWqh, gWqkvThi);
    cudaGetSymbolAddress((void**)&pWql, gWqkvTlo);
    cudaGetSymbolAddress((void**)&pWoh, gWoThi);
    cudaGetSymbolAddress((void**)&pWol, gWoTlo);
    cudaGetSymbolAddress((void**)&pOhi, gOhi);
    cudaGetSymbolAddress((void**)&pOlo, gOlo);

    cudaFuncSetAttribute(attn_mma_kernel,
                         cudaFuncAttributeMaxDynamicSharedMemorySize, ATTN_SMEM);
    cudaFuncSetAttribute(gemm_hmma_kernel<0>,
                         cudaFuncAttributeMaxDynamicSharedMemorySize, GEMM_SMEM);
    cudaFuncSetAttribute(gemm_hmma_kernel<1>,
                         cudaFuncAttributeMaxDynamicSharedMemorySize, GEMM_SMEM);

    // fused input conversions (x split + both weight transposes)
    conv_all_kernel<<<CONV_GRID, 256>>>((const float4*)x, w_qkv, w_out,
                                        pXhi, pXlo, pWqh, pWql, pWoh, pWol);

    // QKV projection -> Q/K/V bf16 hi/lo, [B,H,T,D] (Q pre-scaled 1/8)
    gemm_hmma_kernel<1><<<dim3(N1 / 128, M1 / 128), 256, GEMM_SMEM>>>(
        pXhi, pXlo, pWqh, pWql, b_qkv, nullptr);

    // flash attention -> gOhi/gOlo
    attn_mma_kernel<<<dim3(TT / 128, BB * HH), 256, ATTN_SMEM>>>();

    // output projection -> out
    gemm_hmma_kernel<0><<<dim3(CC / 128, M1 / 128), 256, GEMM_SMEM>>>(
        pOhi, pOlo, pWoh, pWol, b_out, out);
}